// round 12
// baseline (speedup 1.0000x reference)
#include <cuda_runtime.h>
#include <cuda_bf16.h>
#include <cstdint>

// ---------------- problem constants ----------------
#define BB    2048
#define F1N   10
#define F2N   25
#define NTOK  261
#define D4    32
#define GRP   12                 // rows per batch group (h0 + 10*h1 + 1 dummy)
#define MPAD  (BB * GRP)         // 24576 padded GEMM1 rows

// ---------------- scratch (device globals, allocation-free) ----------------
// All tensor scratch stored CHUNK-MAJOR + PRE-SWIZZLED (see swz()).
__device__ __align__(16) __nv_bfloat16 g_Ah[MPAD * 256];
__device__ __align__(16) __nv_bfloat16 g_Al[MPAD * 256];
__device__ __align__(16) __nv_bfloat16 g_A2h[BB * 512];
__device__ __align__(16) __nv_bfloat16 g_A2l[BB * 512];
__device__ __align__(16) __nv_bfloat16 g_W1hT[256 * 256];
__device__ __align__(16) __nv_bfloat16 g_W1lT[256 * 256];
__device__ __align__(16) __nv_bfloat16 g_W2hT[256 * 512];
__device__ __align__(16) __nv_bfloat16 g_W2lT[256 * 512];

// Chunk-major pre-swizzled element offset for logical (row m, col k), k-chunks of 64,
// `rows` rows per chunk. Within a row's 128B chunk-slice, 16B pieces are permuted by
// piece ^= (m & 7) so that a LINEAR bulk copy into smem yields the XOR-swizzled layout
// that ldmatrix consumers address as  r*128 + ((cc ^ (r&7)) << 4).
__device__ __forceinline__ size_t swz(int m, int k, int rows) {
    return (size_t)(k >> 6) * rows * 64 + (size_t)m * 64
         + ((size_t)((((k >> 3) & 7) ^ (m & 7)) << 3)) + (k & 7);
}

// ---------------- PTX helpers (base sm_100-safe: sm_90-era features only) ----------------
__device__ __forceinline__ uint32_t smem_u32(const void* p) {
    uint32_t a;
    asm("{ .reg .u64 t; cvta.to.shared.u64 t, %1; cvt.u32.u64 %0, t; }" : "=r"(a) : "l"(p));
    return a;
}
__device__ __forceinline__ void bulkcp(uint32_t dst, const void* src, uint32_t bytes,
                                       uint32_t mbar) {
    asm volatile(
        "cp.async.bulk.shared::cluster.global.mbarrier::complete_tx::bytes "
        "[%0], [%1], %2, [%3];"
        :: "r"(dst), "l"(src), "r"(bytes), "r"(mbar) : "memory");
}
#define MBARRIER_INIT(mbar, count) \
    asm volatile("mbarrier.init.shared.b64 [%0], %1;" \
                 :: "r"((uint32_t)(mbar)), "r"((uint32_t)(count)) : "memory")
#define MBARRIER_EXPECT_TX(mbar, tx) \
    asm volatile("mbarrier.arrive.expect_tx.shared.b64 _, [%0], %1;" \
                 :: "r"((uint32_t)(mbar)), "r"((uint32_t)(tx)) : "memory")
#define MBARRIER_WAIT_PARITY(mbar, parity) do {                                         \
    uint32_t _m = (uint32_t)(mbar); uint32_t _p = (uint32_t)(parity); uint32_t _d;      \
    asm volatile("{\n\t.reg .pred p;\n\t"                                               \
        "mbarrier.try_wait.parity.acquire.cta.shared::cta.b64 p, [%1], %2;\n\t"         \
        "selp.b32 %0, 1, 0, p;\n\t}" : "=r"(_d) : "r"(_m), "r"(_p) : "memory");         \
    if (!_d) {                                                                           \
        asm volatile("{\n\t.reg .pred P1;\n\t"                                          \
            "WAIT_LOOP_%=:\n\t"                                                          \
            "mbarrier.try_wait.parity.acquire.cta.shared::cta.b64 P1, [%0], %1, 0x989680;\n\t" \
            "@P1 bra.uni WAIT_DONE_%=;\n\t"                                              \
            "bra.uni WAIT_LOOP_%=;\n\t"                                                  \
            "WAIT_DONE_%=:\n\t}" :: "r"(_m), "r"(_p) : "memory");                        \
    } } while (0)

__device__ __forceinline__ void ldsm4(uint32_t* r, uint32_t addr) {
    asm volatile("ldmatrix.sync.aligned.m8n8.x4.shared.b16 {%0,%1,%2,%3}, [%4];"
                 : "=r"(r[0]), "=r"(r[1]), "=r"(r[2]), "=r"(r[3]) : "r"(addr));
}
__device__ __forceinline__ void mma16816(float* c, const uint32_t* a, const uint32_t* b) {
    asm volatile(
        "mma.sync.aligned.m16n8k16.row.col.f32.bf16.bf16.f32 "
        "{%0,%1,%2,%3}, {%4,%5,%6,%7}, {%8,%9}, {%0,%1,%2,%3};"
        : "+f"(c[0]), "+f"(c[1]), "+f"(c[2]), "+f"(c[3])
        : "r"(a[0]), "r"(a[1]), "r"(a[2]), "r"(a[3]), "r"(b[0]), "r"(b[1]));
}

// ---------------- bf16 split helpers ----------------
__device__ __forceinline__ void split1(float w, unsigned short& h, unsigned short& l) {
    __nv_bfloat16 hb = __float2bfloat16_rn(w);
    float r = w - __bfloat162float(hb);
    __nv_bfloat16 lb = __float2bfloat16_rn(r);
    h = __bfloat16_as_ushort(hb);
    l = __bfloat16_as_ushort(lb);
}
// write 4 consecutive-k elements (k % 4 == 0) of row m into A arrays, swizzled layout
__device__ __forceinline__ void storeA4(int m, int k, float4 v) {
    unsigned short hs[4], ls[4];
    float f[4] = {v.x, v.y, v.z, v.w};
#pragma unroll
    for (int i = 0; i < 4; i++) split1(f[i], hs[i], ls[i]);
    size_t o = swz(m, k, MPAD);
    *reinterpret_cast<uint2*>(g_Ah + o) =
        make_uint2((uint32_t)hs[0] | ((uint32_t)hs[1] << 16),
                   (uint32_t)hs[2] | ((uint32_t)hs[3] << 16));
    *reinterpret_cast<uint2*>(g_Al + o) =
        make_uint2((uint32_t)ls[0] | ((uint32_t)ls[1] << 16),
                   (uint32_t)ls[2] | ((uint32_t)ls[3] << 16));
}
// write 2 consecutive-k elements (k % 2 == 0) of row b into A2 arrays, swizzled layout
__device__ __forceinline__ void storeA2_2(int b, int k, float a, float bv) {
    unsigned short h0, l0, h1, l1;
    split1(a, h0, l0);
    split1(bv, h1, l1);
    size_t o = swz(b, k, BB);
    *reinterpret_cast<uint32_t*>(g_A2h + o) = (uint32_t)h0 | ((uint32_t)h1 << 16);
    *reinterpret_cast<uint32_t*>(g_A2l + o) = (uint32_t)l0 | ((uint32_t)l1 << 16);
}

// ---------------- K1: merged weight-prep + neighbor-mean reduce (at HBM floor) ----------------
#define CONVW_BLOCKS 192
__global__ __launch_bounds__(256)
void k_prep(const float4* __restrict__ x4,
            const float* __restrict__ W1, const float* __restrict__ W2) {
    __shared__ float tile[32][33];
    if (blockIdx.x < CONVW_BLOCKS) {
        int t = blockIdx.x;
        const float* W;
        __nv_bfloat16 *OH, *OL;
        int ND = 256, tk, tn;
        if (t < 64) {
            W = W1; OH = g_W1hT; OL = g_W1lT;
            tk = t >> 3; tn = t & 7;
        } else {
            t -= 64;
            W = W2; OH = g_W2hT; OL = g_W2lT;
            tk = t >> 3; tn = t & 7;           // 16 x 8 tiles (KD=512)
        }
        int x = threadIdx.x & 31, y0 = threadIdx.x >> 5;
#pragma unroll
        for (int yy = 0; yy < 4; yy++) {
            int k = tk * 32 + y0 * 4 + yy;
            tile[y0 * 4 + yy][x] = W[(size_t)k * ND + tn * 32 + x];
        }
        __syncthreads();
#pragma unroll
        for (int yy = 0; yy < 4; yy++) {
            int n = tn * 32 + y0 * 4 + yy;
            float v = tile[x][y0 * 4 + yy];
            unsigned short h, l;
            split1(v, h, l);
            size_t o = swz(n, tk * 32 + x, 256);   // chunk-major swizzled [n][k]
            OH[o] = __ushort_as_bfloat16(h);
            OL[o] = __ushort_as_bfloat16(l);
        }
        return;
    }

    const int HOP2_SLOTS = BB * F1N * D4;  // 655360
    int idx = (blockIdx.x - CONVW_BLOCKS) * blockDim.x + threadIdx.x;
    if (idx < HOP2_SLOTS) {
        int d4 = idx & 31;
        int fg = idx >> 5;
        int f = fg % F1N;
        int b = fg / F1N;
        const float4* p = x4 + (size_t)b * NTOK * D4 + (size_t)(1 + F1N + f * F2N) * D4 + d4;
        float4 s[5];
#pragma unroll
        for (int j = 0; j < 5; j++) s[j] = make_float4(0.f, 0.f, 0.f, 0.f);
#pragma unroll
        for (int kb = 0; kb < 5; kb++) {
#pragma unroll
            for (int j = 0; j < 5; j++) {
                float4 v = p[(size_t)(kb * 5 + j) * D4];
                s[j].x += v.x; s[j].y += v.y; s[j].z += v.z; s[j].w += v.w;
            }
        }
        float4 tot = make_float4(
            s[0].x + s[1].x + s[2].x + s[3].x + s[4].x,
            s[0].y + s[1].y + s[2].y + s[3].y + s[4].y,
            s[0].z + s[1].z + s[2].z + s[3].z + s[4].z,
            s[0].w + s[1].w + s[2].w + s[3].w + s[4].w);
        const float inv = 1.0f / (float)F2N;
        int row = b * GRP + 1 + f;
        storeA4(row, 128 + d4 * 4,
                make_float4(tot.x * inv, tot.y * inv, tot.z * inv, tot.w * inv));
    } else {
        int j = idx - HOP2_SLOTS;
        if (j >= BB * D4) return;
        int d4 = j & 31;
        int b = j >> 5;
        const float4* p = x4 + (size_t)b * NTOK * D4;
        int base = b * GRP;
        storeA4(base, d4 * 4, p[d4]);  // seed
        float4 s0 = make_float4(0.f, 0.f, 0.f, 0.f), s1 = s0;
#pragma unroll
        for (int f = 0; f < F1N; f += 2) {
            float4 v0 = p[(size_t)(1 + f) * D4 + d4];
            float4 v1 = p[(size_t)(2 + f) * D4 + d4];
            storeA4(base + 1 + f, d4 * 4, v0);
            storeA4(base + 2 + f, d4 * 4, v1);
            s0.x += v0.x; s0.y += v0.y; s0.z += v0.z; s0.w += v0.w;
            s1.x += v1.x; s1.y += v1.y; s1.z += v1.z; s1.w += v1.w;
        }
        const float inv = 1.0f / (float)F1N;
        storeA4(base, 128 + d4 * 4,
                make_float4((s0.x + s1.x) * inv, (s0.y + s1.y) * inv,
                            (s0.z + s1.z) * inv, (s0.w + s1.w) * inv));
        float4 z = make_float4(0.f, 0.f, 0.f, 0.f);
        storeA4(base + 11, d4 * 4, z);
        storeA4(base + 11, 128 + d4 * 4, z);
    }
}

// ---------------- GEMM1 fused with pooling, bulk-copy pipeline ----------------
// BM=192 (16 groups), BN=256 full-N, grid 128 (1 wave), 768 threads = 24 warps (6M x 4N).
// Per chunk: ONE thread issues 4 cp.async.bulk (Ah/Al 24KB, Bh/Bl 32KB) + mbarrier.
// smem stage s at s*114688: Ah+0, Al+24576, Bh+49152, Bl+81920. mbarriers at 229376.
static constexpr int G1_STAGE  = 114688;
static constexpr int G1_MBAR   = 229376;
static constexpr int G1_SMEM   = 229376 + 64;
static constexpr uint32_t G1_TX = 114688;

__global__ __launch_bounds__(768)
void gemm1_fused(const float* __restrict__ bias) {
    constexpr int SROW = 258;
    extern __shared__ char smem[];
    const uint32_t sb = smem_u32(smem);
    const int tid = threadIdx.x, wid = tid >> 5, lane = tid & 31;
    const int row0 = blockIdx.x * 192;
    const int wm = (wid >> 2) * 32;   // 0..160
    const int wn = (wid & 3) * 64;    // 0..192

    float acc[2][8][4];
#pragma unroll
    for (int mi = 0; mi < 2; mi++)
#pragma unroll
        for (int j = 0; j < 8; j++)
#pragma unroll
            for (int q = 0; q < 4; q++) acc[mi][j][q] = 0.f;

    auto bulk_chunk = [&](int c, int s) {
        const uint32_t base = sb + s * G1_STAGE;
        const uint32_t mb = sb + G1_MBAR + ((c & 1) << 4);
        MBARRIER_EXPECT_TX(mb, G1_TX);
        bulkcp(base,          g_Ah + (size_t)c * MPAD * 64 + (size_t)row0 * 64, 24576, mb);
        bulkcp(base + 24576,  g_Al + (size_t)c * MPAD * 64 + (size_t)row0 * 64, 24576, mb);
        bulkcp(base + 49152,  g_W1hT + (size_t)c * 256 * 64, 32768, mb);
        bulkcp(base + 81920,  g_W1lT + (size_t)c * 256 * 64, 32768, mb);
    };

    if (tid == 0) {
        MBARRIER_INIT(sb + G1_MBAR, 1);
        MBARRIER_INIT(sb + G1_MBAR + 16, 1);
    }
    __syncthreads();
    if (tid == 0) bulk_chunk(0, 0);

    for (int c = 0; c < 4; c++) {
        const int s = c & 1;
        __syncthreads();                      // mma(c-1) done -> stage s^1 free
        if (c < 3 && tid == 0) bulk_chunk(c + 1, s ^ 1);
        MBARRIER_WAIT_PARITY(sb + G1_MBAR + (s << 4), (c >> 1) & 1);

        const uint32_t ah_b = sb + s * G1_STAGE;
        const uint32_t al_b = ah_b + 24576;
        const uint32_t bh_b = ah_b + 49152;
        const uint32_t bl_b = ah_b + 81920;
#pragma unroll
        for (int k16 = 0; k16 < 4; k16++) {
            const int cc = k16 * 2 + (lane >> 4);
            uint32_t ah[2][4], al[2][4], bh[4][4], bl[4][4];
#pragma unroll
            for (int mi = 0; mi < 2; mi++) {
                int r = wm + mi * 16 + (lane & 15);
                uint32_t ad = r * 128 + ((cc ^ (r & 7)) << 4);
                ldsm4(ah[mi], ah_b + ad);
                ldsm4(al[mi], al_b + ad);
            }
#pragma unroll
            for (int ni = 0; ni < 4; ni++) {
                int r = wn + ni * 16 + (lane & 15);
                uint32_t ad = r * 128 + ((cc ^ (r & 7)) << 4);
                ldsm4(bh[ni], bh_b + ad);
                ldsm4(bl[ni], bl_b + ad);
            }
#pragma unroll
            for (int mi = 0; mi < 2; mi++)
#pragma unroll
                for (int j = 0; j < 8; j++) {
                    uint32_t bfh[2] = {bh[j >> 1][j & 1], bh[j >> 1][(j & 1) + 2]};
                    uint32_t bfl[2] = {bl[j >> 1][j & 1], bl[j >> 1][(j & 1) + 2]};
                    mma16816(acc[mi][j], ah[mi], bfh);
                    mma16816(acc[mi][j], ah[mi], bfl);
                    mma16816(acc[mi][j], al[mi], bfh);
                }
        }
    }
    __syncthreads();

    // epilogue: acc (+bias, ReLU) -> smem fp32 tile [192][258]
    float* sacc = reinterpret_cast<float*>(smem);
    const int g = lane >> 2, q = lane & 3;
#pragma unroll
    for (int mi = 0; mi < 2; mi++)
#pragma unroll
        for (int j = 0; j < 8; j++) {
            int ccol = wn + j * 8 + 2 * q;
            float bx = __ldg(bias + ccol);
            float by = __ldg(bias + ccol + 1);
            int r = wm + mi * 16 + g;
            sacc[r * SROW + ccol]           = fmaxf(acc[mi][j][0] + bx, 0.f);
            sacc[r * SROW + ccol + 1]       = fmaxf(acc[mi][j][1] + by, 0.f);
            sacc[(r + 8) * SROW + ccol]     = fmaxf(acc[mi][j][2] + bx, 0.f);
            sacc[(r + 8) * SROW + ccol + 1] = fmaxf(acc[mi][j][3] + by, 0.f);
        }
    __syncthreads();

    // pool: 16 groups x 128 col-pairs -> A2 = [h0 | mean(h1)] split bf16, swizzled layout
#pragma unroll 1
    for (int i = tid; i < 16 * 128; i += 768) {
        int cp = i & 127;
        int grp = i >> 7;
        int c = cp * 2;
        int b = blockIdx.x * 16 + grp;
        const float* rowp = sacc + grp * 12 * SROW + c;
        float h0x = rowp[0], h0y = rowp[1];
        float sx = 0.f, sy = 0.f;
#pragma unroll
        for (int r = 1; r <= 10; r++) {
            sx += rowp[r * SROW];
            sy += rowp[r * SROW + 1];
        }
        storeA2_2(b, c, h0x, h0y);
        storeA2_2(b, c + 256, sx * 0.1f, sy * 0.1f);
    }
}

// ---------------- GEMM2: out = A2 @ W2 + b2, bulk-copy pipeline ----------------
// BM=64, BN=64, K=512 (8 chunks), 256 threads = 8 warps (2M x 4N, warp 32x16).
// smem stage s at s*32768: A2h+0, A2l+8192, W2h+16384, W2l+24576. mbarriers at 65536.
static constexpr int G2_STAGE = 32768;
static constexpr int G2_MBAR  = 65536;
static constexpr int G2_SMEM  = 65536 + 64;
static constexpr uint32_t G2_TX = 32768;

__global__ __launch_bounds__(256)
void gemm2_mma(const float* __restrict__ bias, float* __restrict__ C) {
    extern __shared__ char smem[];
    const uint32_t sb = smem_u32(smem);
    const int tid = threadIdx.x, wid = tid >> 5, lane = tid & 31;
    const int row0 = blockIdx.x * 64, col0 = blockIdx.y * 64;
    const int wm = (wid >> 2) * 32;   // 0,32
    const int wn = (wid & 3) * 16;    // 0..48

    float acc[2][2][4];
#pragma unroll
    for (int mi = 0; mi < 2; mi++)
#pragma unroll
        for (int j = 0; j < 2; j++)
#pragma unroll
            for (int q = 0; q < 4; q++) acc[mi][j][q] = 0.f;

    auto bulk_chunk = [&](int c, int s) {
        const uint32_t base = sb + s * G2_STAGE;
        const uint32_t mb = sb + G2_MBAR + ((c & 1) << 4);
        MBARRIER_EXPECT_TX(mb, G2_TX);
        bulkcp(base,          g_A2h + (size_t)c * BB * 64 + (size_t)row0 * 64, 8192, mb);
        bulkcp(base + 8192,   g_A2l + (size_t)c * BB * 64 + (size_t)row0 * 64, 8192, mb);
        bulkcp(base + 16384,  g_W2hT + ((size_t)c * 256 + col0) * 64, 8192, mb);
        bulkcp(base + 24576,  g_W2lT + ((size_t)c * 256 + col0) * 64, 8192, mb);
    };

    if (tid == 0) {
        MBARRIER_INIT(sb + G2_MBAR, 1);
        MBARRIER_INIT(sb + G2_MBAR + 16, 1);
    }
    __syncthreads();
    if (tid == 0) bulk_chunk(0, 0);

    for (int c = 0; c < 8; c++) {
        const int s = c & 1;
        __syncthreads();
        if (c < 7 && tid == 0) bulk_chunk(c + 1, s ^ 1);
        MBARRIER_WAIT_PARITY(sb + G2_MBAR + (s << 4), (c >> 1) & 1);

        const uint32_t base = sb + s * G2_STAGE;
#pragma unroll
        for (int k16 = 0; k16 < 4; k16++) {
            const int cc = k16 * 2 + (lane >> 4);
            uint32_t ah[2][4], al[2][4], bh[4], bl[4];
#pragma unroll
            for (int mi = 0; mi < 2; mi++) {
                int r = wm + mi * 16 + (lane & 15);
                uint32_t ad = base + r * 128 + ((cc ^ (r & 7)) << 4);
                ldsm4(ah[mi], ad);
                ldsm4(al[mi], ad + 8192);
            }
            {
                int r = wn + (lane & 15);
                uint32_t ad = base + 16384 + r * 128 + ((cc ^ (r & 7)) << 4);
                ldsm4(bh, ad);
                ldsm4(bl, ad + 8192);
            }
#pragma unroll
            for (int mi = 0; mi < 2; mi++)
#pragma unroll
                for (int j = 0; j < 2; j++) {
                    uint32_t bfh[2] = {bh[j], bh[j + 2]};
                    uint32_t bfl[2] = {bl[j], bl[j + 2]};
                    mma16816(acc[mi][j], ah[mi], bfh);
                    mma16816(acc[mi][j], ah[mi], bfl);
                    mma16816(acc[mi][j], al[mi], bfh);
                }
        }
    }

    const int g = lane >> 2, q = lane & 3;
#pragma unroll
    for (int mi = 0; mi < 2; mi++)
#pragma unroll
        for (int j = 0; j < 2; j++) {
            int ccol = col0 + wn + j * 8 + 2 * q;
            float bx = __ldg(bias + ccol), by = __ldg(bias + ccol + 1);
            int r0 = row0 + wm + mi * 16 + g;
            float2 v0 = make_float2(acc[mi][j][0] + bx, acc[mi][j][1] + by);
            float2 v1 = make_float2(acc[mi][j][2] + bx, acc[mi][j][3] + by);
            *reinterpret_cast<float2*>(&C[(size_t)r0 * 256 + ccol]) = v0;
            *reinterpret_cast<float2*>(&C[(size_t)(r0 + 8) * 256 + ccol]) = v1;
        }
}

// ---------------- launch (single stream, 3 kernels) ----------------
extern "C" void kernel_launch(void* const* d_in, const int* in_sizes, int n_in,
                              void* d_out, int out_size) {
    const float* x  = (const float*)d_in[0];
    const float* W1 = (const float*)d_in[1];
    const float* b1 = (const float*)d_in[2];
    const float* W2 = (const float*)d_in[3];
    const float* b2 = (const float*)d_in[4];
    float* out = (float*)d_out;

    cudaFuncSetAttribute((const void*)gemm1_fused,
                         cudaFuncAttributeMaxDynamicSharedMemorySize, G1_SMEM);
    cudaFuncSetAttribute((const void*)gemm2_mma,
                         cudaFuncAttributeMaxDynamicSharedMemorySize, G2_SMEM);

    // K1: merged weight prep (192 blocks) + neighbor-mean reduce (2816 blocks)
    {
        int red_total = BB * F1N * D4 + BB * D4;  // 720896
        int red_blocks = (red_total + 255) / 256; // 2816
        k_prep<<<CONVW_BLOCKS + red_blocks, 256>>>(
            reinterpret_cast<const float4*>(x), W1, W2);
    }
    // GEMM1 + pooling fused, bulk-copy pipeline: grid 128 (1 wave), 768 threads
    gemm1_fused<<<MPAD / 192, 768, G1_SMEM>>>(b1);
    // GEMM2: out = A2 @ W2 + b2, bulk-copy pipeline, grid 32x4
    gemm2_mma<<<dim3(BB / 64, 4), 256, G2_SMEM>>>(b2, out);
}

// round 14
// speedup vs baseline: 1.2484x; 1.2484x over previous
#include <cuda_runtime.h>
#include <cuda_bf16.h>
#include <cstdint>

// ---------------- problem constants ----------------
#define BB    2048
#define F1N   10
#define F2N   25
#define NTOK  261
#define D4    32
#define GRP   12                 // rows per batch group (h0 + 10*h1 + 1 dummy)
#define MPAD  (BB * GRP)         // 24576 padded GEMM1 rows

// ---------------- scratch (device globals, allocation-free) ----------------
__device__ __align__(16) __nv_bfloat16 g_Ah[MPAD * 256];     // row-major [m][256]
__device__ __align__(16) __nv_bfloat16 g_Al[MPAD * 256];
__device__ __align__(16) __nv_bfloat16 g_A2h[BB * 512];      // row-major [b][512]
__device__ __align__(16) __nv_bfloat16 g_A2l[BB * 512];
__device__ __align__(16) __nv_bfloat16 g_W1hT[256 * 256];    // CHUNK-MAJOR PRE-SWIZZLED (bulk src)
__device__ __align__(16) __nv_bfloat16 g_W1lT[256 * 256];
__device__ __align__(16) __nv_bfloat16 g_W2hT[256 * 512];    // row-major [n][512]
__device__ __align__(16) __nv_bfloat16 g_W2lT[256 * 512];

// Chunk-major pre-swizzled element offset (R12-verified): chunk (k>>6), row m slice of
// 64 elems, 16B pieces permuted by ^(m&7) so a LINEAR bulk copy lands in the layout
// consumers address as  r*128 + ((cc ^ (r&7)) << 4).
__device__ __forceinline__ size_t swz(int m, int k, int rows) {
    return (size_t)(k >> 6) * rows * 64 + (size_t)m * 64
         + ((size_t)((((k >> 3) & 7) ^ (m & 7)) << 3)) + (k & 7);
}

// ---------------- PTX helpers (base sm_100-safe) ----------------
__device__ __forceinline__ uint32_t smem_u32(const void* p) {
    uint32_t a;
    asm("{ .reg .u64 t; cvta.to.shared.u64 t, %1; cvt.u32.u64 %0, t; }" : "=r"(a) : "l"(p));
    return a;
}
__device__ __forceinline__ void cp16(uint32_t s, const void* g) {
    asm volatile("cp.async.cg.shared.global [%0], [%1], 16;" :: "r"(s), "l"(g));
}
#define CP_COMMIT() asm volatile("cp.async.commit_group;" ::: "memory")
#define CP_WAIT(n)  asm volatile("cp.async.wait_group %0;" :: "n"(n) : "memory")

__device__ __forceinline__ void bulkcp(uint32_t dst, const void* src, uint32_t bytes,
                                       uint32_t mbar) {
    asm volatile(
        "cp.async.bulk.shared::cluster.global.mbarrier::complete_tx::bytes "
        "[%0], [%1], %2, [%3];"
        :: "r"(dst), "l"(src), "r"(bytes), "r"(mbar) : "memory");
}
#define MBARRIER_INIT(mbar, count) \
    asm volatile("mbarrier.init.shared.b64 [%0], %1;" \
                 :: "r"((uint32_t)(mbar)), "r"((uint32_t)(count)) : "memory")
#define MBARRIER_EXPECT_TX(mbar, tx) \
    asm volatile("mbarrier.arrive.expect_tx.shared.b64 _, [%0], %1;" \
                 :: "r"((uint32_t)(mbar)), "r"((uint32_t)(tx)) : "memory")
#define MBARRIER_WAIT_PARITY(mbar, parity) do {                                         \
    uint32_t _m = (uint32_t)(mbar); uint32_t _p = (uint32_t)(parity); uint32_t _d;      \
    asm volatile("{\n\t.reg .pred p;\n\t"                                               \
        "mbarrier.try_wait.parity.acquire.cta.shared::cta.b64 p, [%1], %2;\n\t"         \
        "selp.b32 %0, 1, 0, p;\n\t}" : "=r"(_d) : "r"(_m), "r"(_p) : "memory");         \
    if (!_d) {                                                                           \
        asm volatile("{\n\t.reg .pred P1;\n\t"                                          \
            "WAIT_LOOP_%=:\n\t"                                                          \
            "mbarrier.try_wait.parity.acquire.cta.shared::cta.b64 P1, [%0], %1, 0x989680;\n\t" \
            "@P1 bra.uni WAIT_DONE_%=;\n\t"                                              \
            "bra.uni WAIT_LOOP_%=;\n\t"                                                  \
            "WAIT_DONE_%=:\n\t}" :: "r"(_m), "r"(_p) : "memory");                        \
    } } while (0)

__device__ __forceinline__ void ldsm4(uint32_t* r, uint32_t addr) {
    asm volatile("ldmatrix.sync.aligned.m8n8.x4.shared.b16 {%0,%1,%2,%3}, [%4];"
                 : "=r"(r[0]), "=r"(r[1]), "=r"(r[2]), "=r"(r[3]) : "r"(addr));
}
__device__ __forceinline__ void mma16816(float* c, const uint32_t* a, const uint32_t* b) {
    asm volatile(
        "mma.sync.aligned.m16n8k16.row.col.f32.bf16.bf16.f32 "
        "{%0,%1,%2,%3}, {%4,%5,%6,%7}, {%8,%9}, {%0,%1,%2,%3};"
        : "+f"(c[0]), "+f"(c[1]), "+f"(c[2]), "+f"(c[3])
        : "r"(a[0]), "r"(a[1]), "r"(a[2]), "r"(a[3]), "r"(b[0]), "r"(b[1]));
}

// ---------------- bf16 split helpers ----------------
__device__ __forceinline__ void split1(float w, unsigned short& h, unsigned short& l) {
    __nv_bfloat16 hb = __float2bfloat16_rn(w);
    float r = w - __bfloat162float(hb);
    __nv_bfloat16 lb = __float2bfloat16_rn(r);
    h = __bfloat16_as_ushort(hb);
    l = __bfloat16_as_ushort(lb);
}
__device__ __forceinline__ void split_store2(__nv_bfloat16* H, __nv_bfloat16* L,
                                             size_t idx, float a, float b) {
    unsigned short h0, l0, h1, l1;
    split1(a, h0, l0);
    split1(b, h1, l1);
    *reinterpret_cast<uint32_t*>(H + idx) = (uint32_t)h0 | ((uint32_t)h1 << 16);
    *reinterpret_cast<uint32_t*>(L + idx) = (uint32_t)l0 | ((uint32_t)l1 << 16);
}
__device__ __forceinline__ void split_store4(__nv_bfloat16* H, __nv_bfloat16* L,
                                             size_t idx, float4 v) {
    unsigned short hs[4], ls[4];
    float f[4] = {v.x, v.y, v.z, v.w};
#pragma unroll
    for (int i = 0; i < 4; i++) split1(f[i], hs[i], ls[i]);
    *reinterpret_cast<uint2*>(H + idx) =
        make_uint2((uint32_t)hs[0] | ((uint32_t)hs[1] << 16),
                   (uint32_t)hs[2] | ((uint32_t)hs[3] << 16));
    *reinterpret_cast<uint2*>(L + idx) =
        make_uint2((uint32_t)ls[0] | ((uint32_t)ls[1] << 16),
                   (uint32_t)ls[2] | ((uint32_t)ls[3] << 16));
}

// ---------------- K1: merged weight-prep + neighbor-mean reduce ----------------
// W1 -> chunk-major pre-swizzled (bulk source); W2 -> row-major [n][512].
#define CONVW_BLOCKS 192
__global__ __launch_bounds__(256)
void k_prep(const float4* __restrict__ x4,
            const float* __restrict__ W1, const float* __restrict__ W2) {
    __shared__ float tile[32][33];
    if (blockIdx.x < CONVW_BLOCKS) {
        int t = blockIdx.x;
        int x = threadIdx.x & 31, y0 = threadIdx.x >> 5;
        if (t < 64) {
            int tk = t >> 3, tn = t & 7;
#pragma unroll
            for (int yy = 0; yy < 4; yy++) {
                int k = tk * 32 + y0 * 4 + yy;
                tile[y0 * 4 + yy][x] = W1[(size_t)k * 256 + tn * 32 + x];
            }
            __syncthreads();
#pragma unroll
            for (int yy = 0; yy < 4; yy++) {
                int n = tn * 32 + y0 * 4 + yy;
                float v = tile[x][y0 * 4 + yy];
                unsigned short h, l;
                split1(v, h, l);
                size_t o = swz(n, tk * 32 + x, 256);   // chunk-major swizzled
                g_W1hT[o] = __ushort_as_bfloat16(h);
                g_W1lT[o] = __ushort_as_bfloat16(l);
            }
        } else {
            t -= 64;
            int tk = t >> 3, tn = t & 7;               // 16 x 8 tiles (KD=512)
#pragma unroll
            for (int yy = 0; yy < 4; yy++) {
                int k = tk * 32 + y0 * 4 + yy;
                tile[y0 * 4 + yy][x] = W2[(size_t)k * 256 + tn * 32 + x];
            }
            __syncthreads();
#pragma unroll
            for (int yy = 0; yy < 4; yy++) {
                int n = tn * 32 + y0 * 4 + yy;
                float v = tile[x][y0 * 4 + yy];
                unsigned short h, l;
                split1(v, h, l);
                size_t o = (size_t)n * 512 + tk * 32 + x;  // row-major
                g_W2hT[o] = __ushort_as_bfloat16(h);
                g_W2lT[o] = __ushort_as_bfloat16(l);
            }
        }
        return;
    }

    const int HOP2_SLOTS = BB * F1N * D4;  // 655360
    int idx = (blockIdx.x - CONVW_BLOCKS) * blockDim.x + threadIdx.x;
    if (idx < HOP2_SLOTS) {
        int d4 = idx & 31;
        int fg = idx >> 5;
        int f = fg % F1N;
        int b = fg / F1N;
        const float4* p = x4 + (size_t)b * NTOK * D4 + (size_t)(1 + F1N + f * F2N) * D4 + d4;
        float4 s[5];
#pragma unroll
        for (int j = 0; j < 5; j++) s[j] = make_float4(0.f, 0.f, 0.f, 0.f);
#pragma unroll
        for (int kb = 0; kb < 5; kb++) {
#pragma unroll
            for (int j = 0; j < 5; j++) {
                float4 v = p[(size_t)(kb * 5 + j) * D4];
                s[j].x += v.x; s[j].y += v.y; s[j].z += v.z; s[j].w += v.w;
            }
        }
        float4 tot = make_float4(
            s[0].x + s[1].x + s[2].x + s[3].x + s[4].x,
            s[0].y + s[1].y + s[2].y + s[3].y + s[4].y,
            s[0].z + s[1].z + s[2].z + s[3].z + s[4].z,
            s[0].w + s[1].w + s[2].w + s[3].w + s[4].w);
        const float inv = 1.0f / (float)F2N;
        size_t row = (size_t)b * GRP + 1 + f;
        split_store4(g_Ah, g_Al, row * 256 + 128 + d4 * 4,
                     make_float4(tot.x * inv, tot.y * inv, tot.z * inv, tot.w * inv));
    } else {
        int j = idx - HOP2_SLOTS;
        if (j >= BB * D4) return;
        int d4 = j & 31;
        int b = j >> 5;
        const float4* p = x4 + (size_t)b * NTOK * D4;
        size_t base = (size_t)b * GRP;
        split_store4(g_Ah, g_Al, base * 256 + d4 * 4, p[d4]);  // seed
        float4 s0 = make_float4(0.f, 0.f, 0.f, 0.f), s1 = s0;
#pragma unroll
        for (int f = 0; f < F1N; f += 2) {
            float4 v0 = p[(size_t)(1 + f) * D4 + d4];
            float4 v1 = p[(size_t)(2 + f) * D4 + d4];
            split_store4(g_Ah, g_Al, (base + 1 + f) * 256 + d4 * 4, v0);
            split_store4(g_Ah, g_Al, (base + 2 + f) * 256 + d4 * 4, v1);
            s0.x += v0.x; s0.y += v0.y; s0.z += v0.z; s0.w += v0.w;
            s1.x += v1.x; s1.y += v1.y; s1.z += v1.z; s1.w += v1.w;
        }
        const float inv = 1.0f / (float)F1N;
        split_store4(g_Ah, g_Al, base * 256 + 128 + d4 * 4,
                     make_float4((s0.x + s1.x) * inv, (s0.y + s1.y) * inv,
                                 (s0.z + s1.z) * inv, (s0.w + s1.w) * inv));
        uint2 z = make_uint2(0u, 0u);
        *reinterpret_cast<uint2*>(g_Ah + (base + 11) * 256 + d4 * 4) = z;
        *reinterpret_cast<uint2*>(g_Al + (base + 11) * 256 + d4 * 4) = z;
        *reinterpret_cast<uint2*>(g_Ah + (base + 11) * 256 + 128 + d4 * 4) = z;
        *reinterpret_cast<uint2*>(g_Al + (base + 11) * 256 + 128 + d4 * 4) = z;
    }
}

// ---------------- GEMM1 fused with pooling: cp.async A + BULK B hybrid ----------------
// BM=96, BN=256 full-N, grid 256, 384 threads (12 warps 3M x 4N, no reg spills).
// A: cp.async double-buffer (2 x 24KB). B: cp.async.bulk double-buffer (2 x 64KB).
// smem: A stage s at s*24576 (Al +12288); B stage s at 49152+s*65536 (Bl +32768);
// mbarriers at 180224. Total 180288.
static constexpr int G1_ASTG = 24576;
static constexpr int G1_BOFF = 49152;
static constexpr int G1_BSTG = 65536;
static constexpr int G1_MBAR = 180224;
static constexpr int G1_SMEM = 180224 + 64;

__global__ __launch_bounds__(384)
void gemm1_fused(const float* __restrict__ bias) {
    constexpr int SROW = 258;
    extern __shared__ char smem[];
    const uint32_t sb = smem_u32(smem);
    const int tid = threadIdx.x, wid = tid >> 5, lane = tid & 31;
    const int row0 = blockIdx.x * 96;
    const int wm = (wid >> 2) * 32;   // 0,32,64
    const int wn = (wid & 3) * 64;    // 0..192

    float acc[2][8][4];
#pragma unroll
    for (int mi = 0; mi < 2; mi++)
#pragma unroll
        for (int j = 0; j < 8; j++)
#pragma unroll
            for (int q = 0; q < 4; q++) acc[mi][j][q] = 0.f;

    auto load_A = [&](int c, int s) {
        const int kofs = c * 64;
        const uint32_t base = sb + s * G1_ASTG;
#pragma unroll
        for (int i = tid; i < 96 * 8; i += 384) {
            int r = i >> 3, cc = i & 7;
            uint32_t sw = r * 128 + ((cc ^ (r & 7)) << 4);
            size_t go = (size_t)(row0 + r) * 256 + kofs + cc * 8;
            cp16(base + sw, g_Ah + go);
            cp16(base + 12288 + sw, g_Al + go);
        }
    };
    auto bulk_B = [&](int c, int s) {
        const uint32_t mb = sb + G1_MBAR + (s << 4);
        const uint32_t bbase = sb + G1_BOFF + s * G1_BSTG;
        MBARRIER_EXPECT_TX(mb, (uint32_t)G1_BSTG);
        bulkcp(bbase,         g_W1hT + (size_t)c * 256 * 64, 32768, mb);
        bulkcp(bbase + 32768, g_W1lT + (size_t)c * 256 * 64, 32768, mb);
    };

    if (tid == 0) {
        MBARRIER_INIT(sb + G1_MBAR, 1);
        MBARRIER_INIT(sb + G1_MBAR + 16, 1);
    }
    __syncthreads();
    load_A(0, 0);
    CP_COMMIT();
    if (tid == 0) bulk_B(0, 0);

    for (int c = 0; c < 4; c++) {
        const int s = c & 1;
        __syncthreads();                 // mma(c-1) finished: stage s^1 free
        if (c < 3) {
            load_A(c + 1, s ^ 1);
            CP_COMMIT();
            if (tid == 0) bulk_B(c + 1, s ^ 1);
            CP_WAIT(1);                  // A_c landed; A_{c+1} in flight
        } else {
            CP_WAIT(0);
        }
        MBARRIER_WAIT_PARITY(sb + G1_MBAR + (s << 4), (c >> 1) & 1);  // B_c landed
        __syncthreads();                 // A visibility across threads

        const uint32_t ah_b = sb + s * G1_ASTG;
        const uint32_t al_b = ah_b + 12288;
        const uint32_t bh_b = sb + G1_BOFF + s * G1_BSTG;
        const uint32_t bl_b = bh_b + 32768;
#pragma unroll
        for (int k16 = 0; k16 < 4; k16++) {
            const int cc = k16 * 2 + (lane >> 4);
            uint32_t ah[2][4], al[2][4], bh[4][4], bl[4][4];
#pragma unroll
            for (int mi = 0; mi < 2; mi++) {
                int r = wm + mi * 16 + (lane & 15);
                uint32_t ad = r * 128 + ((cc ^ (r & 7)) << 4);
                ldsm4(ah[mi], ah_b + ad);
                ldsm4(al[mi], al_b + ad);
            }
#pragma unroll
            for (int ni = 0; ni < 4; ni++) {
                int r = wn + ni * 16 + (lane & 15);
                uint32_t ad = r * 128 + ((cc ^ (r & 7)) << 4);
                ldsm4(bh[ni], bh_b + ad);
                ldsm4(bl[ni], bl_b + ad);
            }
#pragma unroll
            for (int mi = 0; mi < 2; mi++)
#pragma unroll
                for (int j = 0; j < 8; j++) {
                    uint32_t bfh[2] = {bh[j >> 1][j & 1], bh[j >> 1][(j & 1) + 2]};
                    uint32_t bfl[2] = {bl[j >> 1][j & 1], bl[j >> 1][(j & 1) + 2]};
                    mma16816(acc[mi][j], ah[mi], bfh);
                    mma16816(acc[mi][j], ah[mi], bfl);
                    mma16816(acc[mi][j], al[mi], bfh);
                }
        }
    }
    __syncthreads();

    // epilogue: acc (+bias, ReLU) -> smem fp32 tile [96][258]
    float* sacc = reinterpret_cast<float*>(smem);
    const int g = lane >> 2, q = lane & 3;
#pragma unroll
    for (int mi = 0; mi < 2; mi++)
#pragma unroll
        for (int j = 0; j < 8; j++) {
            int ccol = wn + j * 8 + 2 * q;
            float bx = __ldg(bias + ccol);
            float by = __ldg(bias + ccol + 1);
            int r = wm + mi * 16 + g;
            sacc[r * SROW + ccol]           = fmaxf(acc[mi][j][0] + bx, 0.f);
            sacc[r * SROW + ccol + 1]       = fmaxf(acc[mi][j][1] + by, 0.f);
            sacc[(r + 8) * SROW + ccol]     = fmaxf(acc[mi][j][2] + bx, 0.f);
            sacc[(r + 8) * SROW + ccol + 1] = fmaxf(acc[mi][j][3] + by, 0.f);
        }
    __syncthreads();

    // pool: 8 groups x 128 col-pairs -> A2 = [h0 | mean(h1)] split bf16, row-major
#pragma unroll 1
    for (int i = tid; i < 8 * 128; i += 384) {
        int cp = i & 127;
        int grp = i >> 7;
        int c = cp * 2;
        int b = blockIdx.x * 8 + grp;
        const float* rowp = sacc + grp * 12 * SROW + c;
        float h0x = rowp[0], h0y = rowp[1];
        float sx = 0.f, sy = 0.f;
#pragma unroll
        for (int r = 1; r <= 10; r++) {
            sx += rowp[r * SROW];
            sy += rowp[r * SROW + 1];
        }
        size_t ob = (size_t)b * 512 + c;
        split_store2(g_A2h, g_A2l, ob, h0x, h0y);
        split_store2(g_A2h, g_A2l, ob + 256, sx * 0.1f, sy * 0.1f);
    }
}

// ---------------- GEMM2: out = A2 @ W2 + b2 (unchanged, measured-11.6us shape) ----------------
template <int BM, int BN, int KTOT, int WM, int WN>
__global__ __launch_bounds__((BM / WM) * (BN / WN) * 32)
void gemm_mma(const __nv_bfloat16* __restrict__ Ah_g, const __nv_bfloat16* __restrict__ Al_g,
              const __nv_bfloat16* __restrict__ Bh_g, const __nv_bfloat16* __restrict__ Bl_g,
              const float* __restrict__ bias, float* __restrict__ C) {
    constexpr int NTH = (BM / WM) * (BN / WN) * 32;
    constexpr int NCH = KTOT / 64;
    constexpr int SA = BM * 128;
    constexpr int SB = BN * 128;
    constexpr int STAGE = 2 * SA + 2 * SB;
    constexpr int NWN = BN / WN;
    constexpr int MT = WM / 16;
    constexpr int NT8 = WN / 8;
    constexpr int NT16 = WN / 16;

    extern __shared__ char smem[];
    const uint32_t sb = smem_u32(smem);
    const int tid = threadIdx.x, wid = tid >> 5, lane = tid & 31;
    const int row0 = blockIdx.x * BM, col0 = blockIdx.y * BN;
    const int wm = (wid / NWN) * WM;
    const int wn = (wid % NWN) * WN;

    float acc[MT][NT8][4];
#pragma unroll
    for (int mi = 0; mi < MT; mi++)
#pragma unroll
        for (int j = 0; j < NT8; j++)
#pragma unroll
            for (int q = 0; q < 4; q++) acc[mi][j][q] = 0.f;

    auto load_stage = [&](int c, int s) {
        const int kofs = c * 64;
        const uint32_t base = sb + s * STAGE;
#pragma unroll
        for (int i = tid; i < BM * 8; i += NTH) {
            int r = i >> 3, cc = i & 7;
            uint32_t sw = r * 128 + ((cc ^ (r & 7)) << 4);
            size_t go = (size_t)(row0 + r) * KTOT + kofs + cc * 8;
            cp16(base + sw, Ah_g + go);
            cp16(base + SA + sw, Al_g + go);
        }
#pragma unroll
        for (int i = tid; i < BN * 8; i += NTH) {
            int r = i >> 3, cc = i & 7;
            uint32_t sw = r * 128 + ((cc ^ (r & 7)) << 4);
            size_t go = (size_t)(col0 + r) * KTOT + kofs + cc * 8;
            cp16(base + 2 * SA + sw, Bh_g + go);
            cp16(base + 2 * SA + SB + sw, Bl_g + go);
        }
    };

    load_stage(0, 0);
    CP_COMMIT();

    for (int c = 0; c < NCH; c++) {
        const int s = c & 1;
        if (c + 1 < NCH) {
            load_stage(c + 1, s ^ 1);
            CP_COMMIT();
            CP_WAIT(1);
        } else {
            CP_WAIT(0);
        }
        __syncthreads();
        const uint32_t base = sb + s * STAGE;

#pragma unroll
        for (int k16 = 0; k16 < 4; k16++) {
            const int cc = k16 * 2 + (lane >> 4);
            uint32_t ah[MT][4], al[MT][4], bh[NT16][4], bl[NT16][4];
#pragma unroll
            for (int mi = 0; mi < MT; mi++) {
                int r = wm + mi * 16 + (lane & 15);
                uint32_t ad = base + r * 128 + ((cc ^ (r & 7)) << 4);
                ldsm4(ah[mi], ad);
                ldsm4(al[mi], ad + SA);
            }
#pragma unroll
            for (int ni = 0; ni < NT16; ni++) {
                int r = wn + ni * 16 + (lane & 15);
                uint32_t ad = base + 2 * SA + r * 128 + ((cc ^ (r & 7)) << 4);
                ldsm4(bh[ni], ad);
                ldsm4(bl[ni], ad + SB);
            }
#pragma unroll
            for (int mi = 0; mi < MT; mi++)
#pragma unroll
                for (int j = 0; j < NT8; j++) {
                    uint32_t bfh[2] = {bh[j >> 1][j & 1], bh[j >> 1][(j & 1) + 2]};
                    uint32_t bfl[2] = {bl[j >> 1][j & 1], bl[j >> 1][(j & 1) + 2]};
                    mma16816(acc[mi][j], ah[mi], bfh);
                    mma16816(acc[mi][j], ah[mi], bfl);
                    mma16816(acc[mi][j], al[mi], bfh);
                }
        }
        __syncthreads();
    }

    const int g = lane >> 2, q = lane & 3;
#pragma unroll
    for (int mi = 0; mi < MT; mi++)
#pragma unroll
        for (int j = 0; j < NT8; j++) {
            int ccol = col0 + wn + j * 8 + 2 * q;
            float bx = __ldg(bias + ccol), by = __ldg(bias + ccol + 1);
            int r0 = row0 + wm + mi * 16 + g;
            float2 v0 = make_float2(acc[mi][j][0] + bx, acc[mi][j][1] + by);
            float2 v1 = make_float2(acc[mi][j][2] + bx, acc[mi][j][3] + by);
            *reinterpret_cast<float2*>(&C[(size_t)r0 * 256 + ccol]) = v0;
            *reinterpret_cast<float2*>(&C[(size_t)(r0 + 8) * 256 + ccol]) = v1;
        }
}

// ---------------- launch (single stream, 3 kernels) ----------------
static constexpr int SMEM2 = 2 * (2 * 64 * 128 + 2 * 64 * 128);   // 65536

extern "C" void kernel_launch(void* const* d_in, const int* in_sizes, int n_in,
                              void* d_out, int out_size) {
    const float* x  = (const float*)d_in[0];
    const float* W1 = (const float*)d_in[1];
    const float* b1 = (const float*)d_in[2];
    const float* W2 = (const float*)d_in[3];
    const float* b2 = (const float*)d_in[4];
    float* out = (float*)d_out;

    __nv_bfloat16 *a2h, *a2l, *w2h, *w2l;
    cudaGetSymbolAddress((void**)&a2h, g_A2h);
    cudaGetSymbolAddress((void**)&a2l, g_A2l);
    cudaGetSymbolAddress((void**)&w2h, g_W2hT);
    cudaGetSymbolAddress((void**)&w2l, g_W2lT);

    cudaFuncSetAttribute((const void*)gemm1_fused,
                         cudaFuncAttributeMaxDynamicSharedMemorySize, G1_SMEM);
    cudaFuncSetAttribute((const void*)gemm_mma<64, 64, 512, 32, 16>,
                         cudaFuncAttributeMaxDynamicSharedMemorySize, SMEM2);

    // K1: merged weight prep (192 blocks) + neighbor-mean reduce (2816 blocks)
    {
        int red_total = BB * F1N * D4 + BB * D4;  // 720896
        int red_blocks = (red_total + 255) / 256; // 2816
        k_prep<<<CONVW_BLOCKS + red_blocks, 256>>>(
            reinterpret_cast<const float4*>(x), W1, W2);
    }
    // GEMM1 + pooling fused: cp.async A + bulk B, grid 256, 384 threads
    gemm1_fused<<<MPAD / 96, 384, G1_SMEM>>>(b1);
    // GEMM2: out = A2 @ W2 + b2, grid 32x4, 256 thr
    gemm_mma<64, 64, 512, 32, 16>
        <<<dim3(BB / 64, 4), 256, SMEM2>>>(a2h, a2l, w2h, w2l, b2, out);
}

// round 16
// speedup vs baseline: 1.2500x; 1.0013x over previous
#include <cuda_runtime.h>
#include <cuda_bf16.h>
#include <cstdint>

// ---------------- problem constants ----------------
#define BB    2048
#define F1N   10
#define F2N   25
#define NTOK  261
#define D4    32
#define GRP   12                 // rows per batch group (h0 + 10*h1 + 1 dummy)
#define MPAD  (BB * GRP)         // 24576 padded GEMM1 rows

// ---------------- scratch (device globals, allocation-free) ----------------
// ALL GEMM operands stored CHUNK-MAJOR + PRE-SWIZZLED (see swz(); R12-verified).
__device__ __align__(16) __nv_bfloat16 g_Ah[MPAD * 256];
__device__ __align__(16) __nv_bfloat16 g_Al[MPAD * 256];
__device__ __align__(16) __nv_bfloat16 g_A2h[BB * 512];
__device__ __align__(16) __nv_bfloat16 g_A2l[BB * 512];
__device__ __align__(16) __nv_bfloat16 g_W1hT[256 * 256];
__device__ __align__(16) __nv_bfloat16 g_W1lT[256 * 256];
__device__ __align__(16) __nv_bfloat16 g_W2hT[256 * 512];
__device__ __align__(16) __nv_bfloat16 g_W2lT[256 * 512];

// Chunk-major pre-swizzled element offset: chunk (k>>6), row m slice of 64 elems,
// 16B pieces permuted by ^(m&7) so a LINEAR bulk copy into smem yields the layout
// consumers address as  r*128 + ((cc ^ (r&7)) << 4).
__device__ __forceinline__ size_t swz(int m, int k, int rows) {
    return (size_t)(k >> 6) * rows * 64 + (size_t)m * 64
         + ((size_t)((((k >> 3) & 7) ^ (m & 7)) << 3)) + (k & 7);
}

// ---------------- PTX helpers (base sm_100-safe) ----------------
__device__ __forceinline__ uint32_t smem_u32(const void* p) {
    uint32_t a;
    asm("{ .reg .u64 t; cvta.to.shared.u64 t, %1; cvt.u32.u64 %0, t; }" : "=r"(a) : "l"(p));
    return a;
}
__device__ __forceinline__ void bulkcp(uint32_t dst, const void* src, uint32_t bytes,
                                       uint32_t mbar) {
    asm volatile(
        "cp.async.bulk.shared::cluster.global.mbarrier::complete_tx::bytes "
        "[%0], [%1], %2, [%3];"
        :: "r"(dst), "l"(src), "r"(bytes), "r"(mbar) : "memory");
}
#define MBARRIER_INIT(mbar, count) \
    asm volatile("mbarrier.init.shared.b64 [%0], %1;" \
                 :: "r"((uint32_t)(mbar)), "r"((uint32_t)(count)) : "memory")
#define MBARRIER_EXPECT_TX(mbar, tx) \
    asm volatile("mbarrier.arrive.expect_tx.shared.b64 _, [%0], %1;" \
                 :: "r"((uint32_t)(mbar)), "r"((uint32_t)(tx)) : "memory")
#define MBARRIER_WAIT_PARITY(mbar, parity) do {                                         \
    uint32_t _m = (uint32_t)(mbar); uint32_t _p = (uint32_t)(parity); uint32_t _d;      \
    asm volatile("{\n\t.reg .pred p;\n\t"                                               \
        "mbarrier.try_wait.parity.acquire.cta.shared::cta.b64 p, [%1], %2;\n\t"         \
        "selp.b32 %0, 1, 0, p;\n\t}" : "=r"(_d) : "r"(_m), "r"(_p) : "memory");         \
    if (!_d) {                                                                           \
        asm volatile("{\n\t.reg .pred P1;\n\t"                                          \
            "WAIT_LOOP_%=:\n\t"                                                          \
            "mbarrier.try_wait.parity.acquire.cta.shared::cta.b64 P1, [%0], %1, 0x989680;\n\t" \
            "@P1 bra.uni WAIT_DONE_%=;\n\t"                                              \
            "bra.uni WAIT_LOOP_%=;\n\t"                                                  \
            "WAIT_DONE_%=:\n\t}" :: "r"(_m), "r"(_p) : "memory");                        \
    } } while (0)

__device__ __forceinline__ void ldsm4(uint32_t* r, uint32_t addr) {
    asm volatile("ldmatrix.sync.aligned.m8n8.x4.shared.b16 {%0,%1,%2,%3}, [%4];"
                 : "=r"(r[0]), "=r"(r[1]), "=r"(r[2]), "=r"(r[3]) : "r"(addr));
}
__device__ __forceinline__ void mma16816(float* c, const uint32_t* a, const uint32_t* b) {
    asm volatile(
        "mma.sync.aligned.m16n8k16.row.col.f32.bf16.bf16.f32 "
        "{%0,%1,%2,%3}, {%4,%5,%6,%7}, {%8,%9}, {%0,%1,%2,%3};"
        : "+f"(c[0]), "+f"(c[1]), "+f"(c[2]), "+f"(c[3])
        : "r"(a[0]), "r"(a[1]), "r"(a[2]), "r"(a[3]), "r"(b[0]), "r"(b[1]));
}

// ---------------- bf16 split helpers ----------------
__device__ __forceinline__ void split1(float w, unsigned short& h, unsigned short& l) {
    __nv_bfloat16 hb = __float2bfloat16_rn(w);
    float r = w - __bfloat162float(hb);
    __nv_bfloat16 lb = __float2bfloat16_rn(r);
    h = __bfloat16_as_ushort(hb);
    l = __bfloat16_as_ushort(lb);
}
// 4 consecutive-k elems (k%4==0) of row m -> A arrays, chunk-major swizzled
__device__ __forceinline__ void storeA4(int m, int k, float4 v) {
    unsigned short hs[4], ls[4];
    float f[4] = {v.x, v.y, v.z, v.w};
#pragma unroll
    for (int i = 0; i < 4; i++) split1(f[i], hs[i], ls[i]);
    size_t o = swz(m, k, MPAD);
    *reinterpret_cast<uint2*>(g_Ah + o) =
        make_uint2((uint32_t)hs[0] | ((uint32_t)hs[1] << 16),
                   (uint32_t)hs[2] | ((uint32_t)hs[3] << 16));
    *reinterpret_cast<uint2*>(g_Al + o) =
        make_uint2((uint32_t)ls[0] | ((uint32_t)ls[1] << 16),
                   (uint32_t)ls[2] | ((uint32_t)ls[3] << 16));
}
// 2 consecutive-k elems (k%2==0) of row b -> A2 arrays, chunk-major swizzled
__device__ __forceinline__ void storeA2_2(int b, int k, float a, float bv) {
    unsigned short h0, l0, h1, l1;
    split1(a, h0, l0);
    split1(bv, h1, l1);
    size_t o = swz(b, k, BB);
    *reinterpret_cast<uint32_t*>(g_A2h + o) = (uint32_t)h0 | ((uint32_t)h1 << 16);
    *reinterpret_cast<uint32_t*>(g_A2l + o) = (uint32_t)l0 | ((uint32_t)l1 << 16);
}

// ---------------- K1: merged weight-prep + neighbor-mean reduce ----------------
#define CONVW_BLOCKS 192
__global__ __launch_bounds__(256)
void k_prep(const float4* __restrict__ x4,
            const float* __restrict__ W1, const float* __restrict__ W2) {
    __shared__ float tile[32][33];
    if (blockIdx.x < CONVW_BLOCKS) {
        int t = blockIdx.x;
        const float* W;
        __nv_bfloat16 *OH, *OL;
        int WROWS, tk, tn;
        if (t < 64) {
            W = W1; OH = g_W1hT; OL = g_W1lT; WROWS = 256;
            tk = t >> 3; tn = t & 7;
        } else {
            t -= 64;
            W = W2; OH = g_W2hT; OL = g_W2lT; WROWS = 256;   // rows=256 n, K=512
            tk = t >> 3; tn = t & 7;                         // 16 x 8 tiles
        }
        int x = threadIdx.x & 31, y0 = threadIdx.x >> 5;
#pragma unroll
        for (int yy = 0; yy < 4; yy++) {
            int k = tk * 32 + y0 * 4 + yy;
            tile[y0 * 4 + yy][x] = W[(size_t)k * 256 + tn * 32 + x];
        }
        __syncthreads();
#pragma unroll
        for (int yy = 0; yy < 4; yy++) {
            int n = tn * 32 + y0 * 4 + yy;
            float v = tile[x][y0 * 4 + yy];
            unsigned short h, l;
            split1(v, h, l);
            size_t o = swz(n, tk * 32 + x, WROWS);   // chunk-major swizzled
            OH[o] = __ushort_as_bfloat16(h);
            OL[o] = __ushort_as_bfloat16(l);
        }
        return;
    }

    const int HOP2_SLOTS = BB * F1N * D4;  // 655360
    int idx = (blockIdx.x - CONVW_BLOCKS) * blockDim.x + threadIdx.x;
    if (idx < HOP2_SLOTS) {
        int d4 = idx & 31;
        int fg = idx >> 5;
        int f = fg % F1N;
        int b = fg / F1N;
        const float4* p = x4 + (size_t)b * NTOK * D4 + (size_t)(1 + F1N + f * F2N) * D4 + d4;
        float4 s[5];
#pragma unroll
        for (int j = 0; j < 5; j++) s[j] = make_float4(0.f, 0.f, 0.f, 0.f);
#pragma unroll
        for (int kb = 0; kb < 5; kb++) {
#pragma unroll
            for (int j = 0; j < 5; j++) {
                float4 v = p[(size_t)(kb * 5 + j) * D4];
                s[j].x += v.x; s[j].y += v.y; s[j].z += v.z; s[j].w += v.w;
            }
        }
        float4 tot = make_float4(
            s[0].x + s[1].x + s[2].x + s[3].x + s[4].x,
            s[0].y + s[1].y + s[2].y + s[3].y + s[4].y,
            s[0].z + s[1].z + s[2].z + s[3].z + s[4].z,
            s[0].w + s[1].w + s[2].w + s[3].w + s[4].w);
        const float inv = 1.0f / (float)F2N;
        int row = b * GRP + 1 + f;
        storeA4(row, 128 + d4 * 4,
                make_float4(tot.x * inv, tot.y * inv, tot.z * inv, tot.w * inv));
    } else {
        int j = idx - HOP2_SLOTS;
        if (j >= BB * D4) return;
        int d4 = j & 31;
        int b = j >> 5;
        const float4* p = x4 + (size_t)b * NTOK * D4;
        int base = b * GRP;
        storeA4(base, d4 * 4, p[d4]);  // seed
        float4 s0 = make_float4(0.f, 0.f, 0.f, 0.f), s1 = s0;
#pragma unroll
        for (int f = 0; f < F1N; f += 2) {
            float4 v0 = p[(size_t)(1 + f) * D4 + d4];
            float4 v1 = p[(size_t)(2 + f) * D4 + d4];
            storeA4(base + 1 + f, d4 * 4, v0);
            storeA4(base + 2 + f, d4 * 4, v1);
            s0.x += v0.x; s0.y += v0.y; s0.z += v0.z; s0.w += v0.w;
            s1.x += v1.x; s1.y += v1.y; s1.z += v1.z; s1.w += v1.w;
        }
        const float inv = 1.0f / (float)F1N;
        storeA4(base, 128 + d4 * 4,
                make_float4((s0.x + s1.x) * inv, (s0.y + s1.y) * inv,
                            (s0.z + s1.z) * inv, (s0.w + s1.w) * inv));
        float4 z = make_float4(0.f, 0.f, 0.f, 0.f);
        storeA4(base + 11, d4 * 4, z);
        storeA4(base + 11, 128 + d4 * 4, z);
    }
}

// ---------------- GEMM1 fused with pooling: ALL-BULK loads ----------------
// BM=96, BN=256 full-N, grid 256, 384 threads (no reg spills).
// Per chunk one thread issues 4 cp.async.bulk: Ah/Al 12KB + Bh/Bl 32KB, tx=90112.
// smem stage s at s*90112: Ah+0, Al+12288, Bh+24576, Bl+57344. mbarriers at 180224.
static constexpr int G1_STAGE = 90112;
static constexpr int G1_MBAR  = 180224;
static constexpr int G1_SMEM  = 180224 + 64;

__global__ __launch_bounds__(384)
void gemm1_fused(const float* __restrict__ bias) {
    constexpr int SROW = 258;
    extern __shared__ char smem[];
    const uint32_t sb = smem_u32(smem);
    const int tid = threadIdx.x, wid = tid >> 5, lane = tid & 31;
    const int row0 = blockIdx.x * 96;
    const int wm = (wid >> 2) * 32;   // 0,32,64
    const int wn = (wid & 3) * 64;    // 0..192

    float acc[2][8][4];
#pragma unroll
    for (int mi = 0; mi < 2; mi++)
#pragma unroll
        for (int j = 0; j < 8; j++)
#pragma unroll
            for (int q = 0; q < 4; q++) acc[mi][j][q] = 0.f;

    auto bulk_chunk = [&](int c, int s) {
        const uint32_t base = sb + s * G1_STAGE;
        const uint32_t mb = sb + G1_MBAR + (s << 4);
        MBARRIER_EXPECT_TX(mb, (uint32_t)G1_STAGE);
        bulkcp(base,          g_Ah + (size_t)c * MPAD * 64 + (size_t)row0 * 64, 12288, mb);
        bulkcp(base + 12288,  g_Al + (size_t)c * MPAD * 64 + (size_t)row0 * 64, 12288, mb);
        bulkcp(base + 24576,  g_W1hT + (size_t)c * 256 * 64, 32768, mb);
        bulkcp(base + 57344,  g_W1lT + (size_t)c * 256 * 64, 32768, mb);
    };

    if (tid == 0) {
        MBARRIER_INIT(sb + G1_MBAR, 1);
        MBARRIER_INIT(sb + G1_MBAR + 16, 1);
    }
    __syncthreads();
    if (tid == 0) bulk_chunk(0, 0);

    for (int c = 0; c < 4; c++) {
        const int s = c & 1;
        __syncthreads();                 // mma(c-1) finished: stage s^1 free for prefetch
        if (c < 3 && tid == 0) bulk_chunk(c + 1, s ^ 1);
        MBARRIER_WAIT_PARITY(sb + G1_MBAR + (s << 4), (c >> 1) & 1);

        const uint32_t ah_b = sb + s * G1_STAGE;
        const uint32_t al_b = ah_b + 12288;
        const uint32_t bh_b = ah_b + 24576;
        const uint32_t bl_b = ah_b + 57344;
#pragma unroll
        for (int k16 = 0; k16 < 4; k16++) {
            const int cc = k16 * 2 + (lane >> 4);
            uint32_t ah[2][4], al[2][4], bh[4][4], bl[4][4];
#pragma unroll
            for (int mi = 0; mi < 2; mi++) {
                int r = wm + mi * 16 + (lane & 15);
                uint32_t ad = r * 128 + ((cc ^ (r & 7)) << 4);
                ldsm4(ah[mi], ah_b + ad);
                ldsm4(al[mi], al_b + ad);
            }
#pragma unroll
            for (int ni = 0; ni < 4; ni++) {
                int r = wn + ni * 16 + (lane & 15);
                uint32_t ad = r * 128 + ((cc ^ (r & 7)) << 4);
                ldsm4(bh[ni], bh_b + ad);
                ldsm4(bl[ni], bl_b + ad);
            }
#pragma unroll
            for (int mi = 0; mi < 2; mi++)
#pragma unroll
                for (int j = 0; j < 8; j++) {
                    uint32_t bfh[2] = {bh[j >> 1][j & 1], bh[j >> 1][(j & 1) + 2]};
                    uint32_t bfl[2] = {bl[j >> 1][j & 1], bl[j >> 1][(j & 1) + 2]};
                    mma16816(acc[mi][j], ah[mi], bfh);
                    mma16816(acc[mi][j], ah[mi], bfl);
                    mma16816(acc[mi][j], al[mi], bfh);
                }
        }
    }
    __syncthreads();

    // epilogue: acc (+bias, ReLU) -> smem fp32 tile [96][258]
    float* sacc = reinterpret_cast<float*>(smem);
    const int g = lane >> 2, q = lane & 3;
#pragma unroll
    for (int mi = 0; mi < 2; mi++)
#pragma unroll
        for (int j = 0; j < 8; j++) {
            int ccol = wn + j * 8 + 2 * q;
            float bx = __ldg(bias + ccol);
            float by = __ldg(bias + ccol + 1);
            int r = wm + mi * 16 + g;
            sacc[r * SROW + ccol]           = fmaxf(acc[mi][j][0] + bx, 0.f);
            sacc[r * SROW + ccol + 1]       = fmaxf(acc[mi][j][1] + by, 0.f);
            sacc[(r + 8) * SROW + ccol]     = fmaxf(acc[mi][j][2] + bx, 0.f);
            sacc[(r + 8) * SROW + ccol + 1] = fmaxf(acc[mi][j][3] + by, 0.f);
        }
    __syncthreads();

    // pool: 8 groups x 128 col-pairs -> A2 = [h0 | mean(h1)], chunk-major swizzled
#pragma unroll 1
    for (int i = tid; i < 8 * 128; i += 384) {
        int cp = i & 127;
        int grp = i >> 7;
        int c = cp * 2;
        int b = blockIdx.x * 8 + grp;
        const float* rowp = sacc + grp * 12 * SROW + c;
        float h0x = rowp[0], h0y = rowp[1];
        float sx = 0.f, sy = 0.f;
#pragma unroll
        for (int r = 1; r <= 10; r++) {
            sx += rowp[r * SROW];
            sy += rowp[r * SROW + 1];
        }
        storeA2_2(b, c, h0x, h0y);
        storeA2_2(b, c + 256, sx * 0.1f, sy * 0.1f);
    }
}

// ---------------- GEMM2: out = A2 @ W2 + b2, ALL-BULK (R12-verified) ----------------
// BM=64, BN=64, K=512 (8 chunks), 256 threads = 8 warps (2M x 4N, warp 32x16).
// smem stage s at s*32768: A2h+0, A2l+8192, W2h+16384, W2l+24576. mbarriers at 65536.
static constexpr int G2_STAGE = 32768;
static constexpr int G2_MBAR  = 65536;
static constexpr int G2_SMEM  = 65536 + 64;

__global__ __launch_bounds__(256)
void gemm2_mma(const float* __restrict__ bias, float* __restrict__ C) {
    extern __shared__ char smem[];
    const uint32_t sb = smem_u32(smem);
    const int tid = threadIdx.x, wid = tid >> 5, lane = tid & 31;
    const int row0 = blockIdx.x * 64, col0 = blockIdx.y * 64;
    const int wm = (wid >> 2) * 32;   // 0,32
    const int wn = (wid & 3) * 16;    // 0..48

    float acc[2][2][4];
#pragma unroll
    for (int mi = 0; mi < 2; mi++)
#pragma unroll
        for (int j = 0; j < 2; j++)
#pragma unroll
            for (int q = 0; q < 4; q++) acc[mi][j][q] = 0.f;

    auto bulk_chunk = [&](int c, int s) {
        const uint32_t base = sb + s * G2_STAGE;
        const uint32_t mb = sb + G2_MBAR + (s << 4);
        MBARRIER_EXPECT_TX(mb, (uint32_t)G2_STAGE);
        bulkcp(base,          g_A2h + (size_t)c * BB * 64 + (size_t)row0 * 64, 8192, mb);
        bulkcp(base + 8192,   g_A2l + (size_t)c * BB * 64 + (size_t)row0 * 64, 8192, mb);
        bulkcp(base + 16384,  g_W2hT + ((size_t)c * 256 + col0) * 64, 8192, mb);
        bulkcp(base + 24576,  g_W2lT + ((size_t)c * 256 + col0) * 64, 8192, mb);
    };

    if (tid == 0) {
        MBARRIER_INIT(sb + G2_MBAR, 1);
        MBARRIER_INIT(sb + G2_MBAR + 16, 1);
    }
    __syncthreads();
    if (tid == 0) bulk_chunk(0, 0);

    for (int c = 0; c < 8; c++) {
        const int s = c & 1;
        __syncthreads();
        if (c < 7 && tid == 0) bulk_chunk(c + 1, s ^ 1);
        MBARRIER_WAIT_PARITY(sb + G2_MBAR + (s << 4), (c >> 1) & 1);

        const uint32_t base = sb + s * G2_STAGE;
#pragma unroll
        for (int k16 = 0; k16 < 4; k16++) {
            const int cc = k16 * 2 + (lane >> 4);
            uint32_t ah[2][4], al[2][4], bh[4], bl[4];
#pragma unroll
            for (int mi = 0; mi < 2; mi++) {
                int r = wm + mi * 16 + (lane & 15);
                uint32_t ad = base + r * 128 + ((cc ^ (r & 7)) << 4);
                ldsm4(ah[mi], ad);
                ldsm4(al[mi], ad + 8192);
            }
            {
                int r = wn + (lane & 15);
                uint32_t ad = base + 16384 + r * 128 + ((cc ^ (r & 7)) << 4);
                ldsm4(bh, ad);
                ldsm4(bl, ad + 8192);
            }
#pragma unroll
            for (int mi = 0; mi < 2; mi++)
#pragma unroll
                for (int j = 0; j < 2; j++) {
                    uint32_t bfh[2] = {bh[j], bh[j + 2]};
                    uint32_t bfl[2] = {bl[j], bl[j + 2]};
                    mma16816(acc[mi][j], ah[mi], bfh);
                    mma16816(acc[mi][j], ah[mi], bfl);
                    mma16816(acc[mi][j], al[mi], bfh);
                }
        }
    }

    const int g = lane >> 2, q = lane & 3;
#pragma unroll
    for (int mi = 0; mi < 2; mi++)
#pragma unroll
        for (int j = 0; j < 2; j++) {
            int ccol = col0 + wn + j * 8 + 2 * q;
            float bx = __ldg(bias + ccol), by = __ldg(bias + ccol + 1);
            int r0 = row0 + wm + mi * 16 + g;
            float2 v0 = make_float2(acc[mi][j][0] + bx, acc[mi][j][1] + by);
            float2 v1 = make_float2(acc[mi][j][2] + bx, acc[mi][j][3] + by);
            *reinterpret_cast<float2*>(&C[(size_t)r0 * 256 + ccol]) = v0;
            *reinterpret_cast<float2*>(&C[(size_t)(r0 + 8) * 256 + ccol]) = v1;
        }
}

// ---------------- launch (single stream, 3 kernels) ----------------
extern "C" void kernel_launch(void* const* d_in, const int* in_sizes, int n_in,
                              void* d_out, int out_size) {
    const float* x  = (const float*)d_in[0];
    const float* W1 = (const float*)d_in[1];
    const float* b1 = (const float*)d_in[2];
    const float* W2 = (const float*)d_in[3];
    const float* b2 = (const float*)d_in[4];
    float* out = (float*)d_out;

    cudaFuncSetAttribute((const void*)gemm1_fused,
                         cudaFuncAttributeMaxDynamicSharedMemorySize, G1_SMEM);
    cudaFuncSetAttribute((const void*)gemm2_mma,
                         cudaFuncAttributeMaxDynamicSharedMemorySize, G2_SMEM);

    // K1: merged weight prep (192 blocks) + neighbor-mean reduce (2816 blocks)
    {
        int red_total = BB * F1N * D4 + BB * D4;  // 720896
        int red_blocks = (red_total + 255) / 256; // 2816
        k_prep<<<CONVW_BLOCKS + red_blocks, 256>>>(
            reinterpret_cast<const float4*>(x), W1, W2);
    }
    // GEMM1 + pooling fused: all-bulk loads, grid 256, 384 threads
    gemm1_fused<<<MPAD / 96, 384, G1_SMEM>>>(b1);
    // GEMM2: out = A2 @ W2 + b2, all-bulk, grid 32x4, 256 thr
    gemm2_mma<<<dim3(BB / 64, 4), 256, G2_SMEM>>>(b2, out);
}